// round 4
// baseline (speedup 1.0000x reference)
#include <cuda_runtime.h>

#define HH 2048
#define WW 2048
#define HWT (HH*WW)
#define RD 7
#define RG 60
#define KSEL 4195u          /* (H*W)//1000 + 1 : rank of threshold (1-based from top) */
#define OMEGA 0.95f
#define EPSG 1e-4f

// ---------------- scratch (device globals; no allocation) ----------------
__device__ float    g_dch[HWT];            // horizontal-min intermediate
__device__ float    g_dc[HWT];             // dark channel
__device__ float    g_vsum[10*HWT];        // 10 vertically box-summed planes (160MB)
__device__ unsigned g_hist1[2048];         // coarse bins: float bits >> 19
__device__ unsigned g_hist2b[524288];      // fine bins: low 19 bits (within coarse bin)
__device__ unsigned g_selKey;
__device__ unsigned g_selRank;
__device__ float    g_thres;
__device__ unsigned g_cnt;
__device__ float    g_sumr, g_sumg, g_sumb;
__device__ float    g_avg, g_invavg;

// ---------------- init: zero histograms / accumulators ----------------
__global__ void k_init() {
    int i = blockIdx.x * blockDim.x + threadIdx.x;
    if (i < 524288) g_hist2b[i] = 0u;
    if (i < 2048)   g_hist1[i]  = 0u;
    if (i == 0) {
        g_cnt = 0u; g_sumr = 0.f; g_sumg = 0.f; g_sumb = 0.f;
        g_selKey = 0u; g_selRank = 0u; g_thres = 0.f;
    }
}

// ---------------- channel-min + horizontal min (r=7) ----------------
__global__ void __launch_bounds__(256) k_cmin_hmin(const float* __restrict__ x) {
    __shared__ float s[256 + 2*RD];
    int row = blockIdx.y;
    int x0  = blockIdx.x * 256;
    int t   = threadIdx.x;
    for (int i = t; i < 256 + 2*RD; i += 256) {
        int xx = x0 - RD + i;
        float v = 1e30f;
        if (xx >= 0 && xx < WW) {
            float r = x[0*HWT + row*WW + xx];
            float g = x[1*HWT + row*WW + xx];
            float b = x[2*HWT + row*WW + xx];
            v = fminf(r, fminf(g, b));
        }
        s[i] = v;
    }
    __syncthreads();
    float m = s[t];
#pragma unroll
    for (int j = 1; j <= 2*RD; j++) m = fminf(m, s[t + j]);
    g_dch[row*WW + x0 + t] = m;
}

// ---------------- vertical min (r=7) ----------------
__global__ void __launch_bounds__(256) k_vmin() {
    __shared__ float s[16 + 2*RD][256];
    int xx = blockIdx.x * 256 + threadIdx.x;
    int y0 = blockIdx.y * 16;
    for (int r = 0; r < 16 + 2*RD; r++) {
        int yy = y0 - RD + r;
        s[r][threadIdx.x] = (yy >= 0 && yy < HH) ? g_dch[yy*WW + xx] : 1e30f;
    }
    __syncthreads();
    for (int k = 0; k < 16; k++) {
        float m = s[k][threadIdx.x];
#pragma unroll
        for (int j = 1; j <= 2*RD; j++) m = fminf(m, s[k + j][threadIdx.x]);
        g_dc[(y0 + k)*WW + xx] = m;
    }
}

// ---------------- histogram pass 1: coarse bins (bits>>19), smem private ----------------
__global__ void __launch_bounds__(256) k_hist1() {
    __shared__ unsigned sh[2048];
    int t = threadIdx.x;
    for (int i = t; i < 2048; i += 256) sh[i] = 0u;
    __syncthreads();
    int tid = blockIdx.x * 256 + t;
    int stride = gridDim.x * 256;
    int lane = t & 31;
    for (int i = tid; i < HWT; i += stride) {
        unsigned key = __float_as_uint(g_dc[i]) >> 19;   // < 2048 for dc in [0,1)
        unsigned prev = __shfl_up_sync(0xffffffffu, key, 1);
        bool leader = (lane == 0) || (key != prev);
        unsigned bal = __ballot_sync(0xffffffffu, leader);
        if (leader) {
            unsigned above = (lane == 31) ? 0u : (bal >> (lane + 1));
            int run = above ? __ffs((int)above) : (32 - lane);
            atomicAdd(&sh[key], (unsigned)run);
        }
    }
    __syncthreads();
    for (int i = t; i < 2048; i += 256) {
        unsigned v = sh[i];
        if (v) atomicAdd(&g_hist1[i], v);
    }
}

// ---------------- find coarse bin containing the KSEL-th largest ----------------
__global__ void k_scan1() {
    __shared__ unsigned part[256];
    int t = threadIdx.x;
    int base = 2047 - 8 * t;
    unsigned sum = 0;
    for (int j = 0; j < 8; j++) sum += g_hist1[base - j];
    part[t] = sum;
    __syncthreads();
    if (t == 0) {
        unsigned cum = 0; int sel = 0;
        for (int i = 0; i < 256; i++) {
            if (cum + part[i] >= KSEL) { sel = i; break; }
            cum += part[i];
        }
        int hb = 2047 - 8 * sel;
        for (int j = 0; j < 8; j++) {
            unsigned h = g_hist1[hb - j];
            if (cum + h >= KSEL) {
                g_selKey = (unsigned)(hb - j);
                g_selRank = KSEL - cum;
                break;
            }
            cum += h;
        }
    }
}

// ---------------- histogram pass 2: low 19 bits within selected coarse bin ----------------
__global__ void k_hist2() {
    unsigned B = g_selKey;
    int tid = blockIdx.x * blockDim.x + threadIdx.x;
    int stride = gridDim.x * blockDim.x;
    for (int i = tid; i < HWT; i += stride) {
        unsigned bits = __float_as_uint(g_dc[i]);
        if ((bits >> 19) == B) atomicAdd(&g_hist2b[bits & 0x7FFFFu], 1u);
    }
}

// ---------------- find exact threshold value (full 32 bits) ----------------
__global__ void __launch_bounds__(1024) k_scan2() {
    __shared__ unsigned part[1024];
    unsigned K = g_selRank;
    int t = threadIdx.x;
    int base = 524287 - 512 * t;
    unsigned sum = 0;
    for (int j = 0; j < 512; j++) sum += g_hist2b[base - j];
    part[t] = sum;
    __syncthreads();
    if (t == 0) {
        unsigned cum = 0; int sel = 0;
        for (int i = 0; i < 1024; i++) {
            if (cum + part[i] >= K) { sel = i; break; }
            cum += part[i];
        }
        int hb = 524287 - 512 * sel;
        for (int j = 0; j < 512; j++) {
            unsigned h = g_hist2b[hb - j];
            if (cum + h >= K) {
                g_thres = __uint_as_float((g_selKey << 19) | (unsigned)(hb - j));
                break;
            }
            cum += h;
        }
    }
}

// ---------------- masked sums for atmospheric light ----------------
__global__ void k_mask(const float* __restrict__ x) {
    float th = g_thres;
    int tid = blockIdx.x * blockDim.x + threadIdx.x;
    int stride = gridDim.x * blockDim.x;
    unsigned cnt = 0; float sr = 0.f, sg = 0.f, sb = 0.f;
    for (int i = tid; i < HWT; i += stride) {
        if (g_dc[i] >= th) {
            cnt++;
            sr += x[i];
            sg += x[HWT + i];
            sb += x[2*HWT + i];
        }
    }
#pragma unroll
    for (int o = 16; o > 0; o >>= 1) {
        cnt += __shfl_down_sync(0xffffffffu, cnt, o);
        sr  += __shfl_down_sync(0xffffffffu, sr,  o);
        sg  += __shfl_down_sync(0xffffffffu, sg,  o);
        sb  += __shfl_down_sync(0xffffffffu, sb,  o);
    }
    if ((threadIdx.x & 31) == 0) {
        atomicAdd(&g_cnt, cnt);
        atomicAdd(&g_sumr, sr);
        atomicAdd(&g_sumg, sg);
        atomicAdd(&g_sumb, sb);
    }
}

__global__ void k_avg() {
    float c = (float)g_cnt;
    float avg = (0.299f * g_sumr + 0.587f * g_sumg + 0.114f * g_sumb) / c;
    g_avg = avg;
    g_invavg = 1.0f / avg;
}

// ---------------- compute one row's 10 plane values (float2 per thread) ----------------
__device__ __forceinline__ void vrow(const float* __restrict__ x, int yy, int c0,
                                     float inva, float2 v[10]) {
    float2 a0 = *(const float2*)(x + 0*HWT + yy*WW + c0);
    float2 a1 = *(const float2*)(x + 1*HWT + yy*WW + c0);
    float2 a2 = *(const float2*)(x + 2*HWT + yy*WW + c0);
    float2 d  = *(const float2*)(g_dc + yy*WW + c0);
    float px = fmaf(-OMEGA * inva, d.x, 1.0f);
    float py = fmaf(-OMEGA * inva, d.y, 1.0f);
    v[0] = make_float2(px, py);
    v[1] = a0; v[2] = a1; v[3] = a2;
    v[4] = make_float2(px * a0.x, py * a0.y);
    v[5] = make_float2(px * a1.x, py * a1.y);
    v[6] = make_float2(px * a2.x, py * a2.y);
    v[7] = make_float2(a0.x * a0.x, a0.y * a0.y);
    v[8] = make_float2(a1.x * a1.x, a1.y * a1.y);
    v[9] = make_float2(a2.x * a2.x, a2.y * a2.y);
}

// ---------------- vertical rolling box sums of the 10 planes ----------------
__global__ void __launch_bounds__(128) k_vpass(const float* __restrict__ x) {
    const int S = 64;
    int c0 = (blockIdx.x * 128 + threadIdx.x) * 2;
    int y0 = blockIdx.y * S;
    float inva = g_invavg;
    float2 s[10];
#pragma unroll
    for (int p = 0; p < 10; p++) s[p] = make_float2(0.f, 0.f);

    int ylo = y0 - RG; if (ylo < 0) ylo = 0;
    int yhi = y0 + RG; if (yhi > HH - 1) yhi = HH - 1;
#pragma unroll 4
    for (int yy = ylo; yy <= yhi; yy++) {
        float2 v[10];
        vrow(x, yy, c0, inva, v);
#pragma unroll
        for (int p = 0; p < 10; p++) { s[p].x += v[p].x; s[p].y += v[p].y; }
    }
    for (int k = 0; k < S; k++) {
        int y = y0 + k;
        if (k > 0) {
            int ya = y + RG;
            if (ya < HH) {
                float2 v[10];
                vrow(x, ya, c0, inva, v);
#pragma unroll
                for (int p = 0; p < 10; p++) { s[p].x += v[p].x; s[p].y += v[p].y; }
            }
            int yr = y - RG - 1;
            if (yr >= 0) {
                float2 v[10];
                vrow(x, yr, c0, inva, v);
#pragma unroll
                for (int p = 0; p < 10; p++) { s[p].x -= v[p].x; s[p].y -= v[p].y; }
            }
        }
#pragma unroll
        for (int p = 0; p < 10; p++)
            *(float2*)(g_vsum + p*HWT + y*WW + c0) = s[p];
    }
}

// ---------------- horizontal box sums (block scans) + full epilogue ----------------
// one block per half-row: 1024 output cols + 60-col halo each side, zero-padded
#define SEG 1144
__global__ void __launch_bounds__(256) k_hfinal(const float* __restrict__ x,
                                                float* __restrict__ out) {
    __shared__ float sps[10][SEG];
    __shared__ float wpart[8];
    int row = blockIdx.y;
    int c0  = blockIdx.x * 1024;
    int s0  = c0 - RG;
    int t = threadIdx.x, lane = t & 31, wid = t >> 5;

    for (int pl = 0; pl < 10; pl++) {
        const float* __restrict__ src = g_vsum + pl*HWT + row*WW;
        float carry = 0.f;
        for (int ch = 0; ch < 5; ch++) {
            int L = ch * 256 + t;
            int gc = s0 + L;
            float v = 0.f;
            if (L < SEG && gc >= 0 && gc < WW) v = src[gc];
            float sc = v;
#pragma unroll
            for (int o = 1; o < 32; o <<= 1) {
                float n = __shfl_up_sync(0xffffffffu, sc, o);
                if (lane >= o) sc += n;
            }
            if (lane == 31) wpart[wid] = sc;
            __syncthreads();
            float off = carry, tot = 0.f;
#pragma unroll
            for (int w = 0; w < 8; w++) {
                float pw = wpart[w];
                tot += pw;
                if (w < wid) off += pw;
            }
            if (L < SEG) sps[pl][L] = sc + off;
            carry += tot;
            __syncthreads();
        }
    }

    float avg = g_avg;
    int ny = min(row + RG, HH - 1) - max(row - RG, 0) + 1;
#pragma unroll
    for (int j = 0; j < 4; j++) {
        int L = t + j * 256;          // 0..1023
        int gc = c0 + L;
        int hi = L + 2*RG;            // local index of gc+RG
        int lo = L - 1;               // local index of gc-RG-1
        float w0 = sps[0][hi] - (lo >= 0 ? sps[0][lo] : 0.f);
        float w1 = sps[1][hi] - (lo >= 0 ? sps[1][lo] : 0.f);
        float w2 = sps[2][hi] - (lo >= 0 ? sps[2][lo] : 0.f);
        float w3 = sps[3][hi] - (lo >= 0 ? sps[3][lo] : 0.f);
        float w4 = sps[4][hi] - (lo >= 0 ? sps[4][lo] : 0.f);
        float w5 = sps[5][hi] - (lo >= 0 ? sps[5][lo] : 0.f);
        float w6 = sps[6][hi] - (lo >= 0 ? sps[6][lo] : 0.f);
        float w7 = sps[7][hi] - (lo >= 0 ? sps[7][lo] : 0.f);
        float w8 = sps[8][hi] - (lo >= 0 ? sps[8][lo] : 0.f);
        float w9 = sps[9][hi] - (lo >= 0 ? sps[9][lo] : 0.f);
        int nx = min(gc + RG, WW - 1) - max(gc - RG, 0) + 1;
        float invN = __fdividef(1.0f, (float)(nx * ny));
        float mp = w0 * invN;
        float mi, mpi, mii, cip, cii, a, b, xi, rt, yv;
        // ch 0
        mi = w1 * invN; mpi = w4 * invN; mii = w7 * invN;
        cip = mpi - mp * mi; cii = mii - mi * mi;
        a = __fdividef(cip, cii + EPSG); b = mp - a * mi;
        xi = x[0*HWT + row*WW + gc];
        rt = fminf(fmaxf(a * xi + b, 0.0f), 1.0f); rt = fmaxf(rt, 0.1f);
        yv = __fdividef(xi - avg, rt) + avg;
        out[0*HWT + row*WW + gc] = fminf(fmaxf(yv, 0.0f), 1.0f);
        // ch 1
        mi = w2 * invN; mpi = w5 * invN; mii = w8 * invN;
        cip = mpi - mp * mi; cii = mii - mi * mi;
        a = __fdividef(cip, cii + EPSG); b = mp - a * mi;
        xi = x[1*HWT + row*WW + gc];
        rt = fminf(fmaxf(a * xi + b, 0.0f), 1.0f); rt = fmaxf(rt, 0.1f);
        yv = __fdividef(xi - avg, rt) + avg;
        out[1*HWT + row*WW + gc] = fminf(fmaxf(yv, 0.0f), 1.0f);
        // ch 2
        mi = w3 * invN; mpi = w6 * invN; mii = w9 * invN;
        cip = mpi - mp * mi; cii = mii - mi * mi;
        a = __fdividef(cip, cii + EPSG); b = mp - a * mi;
        xi = x[2*HWT + row*WW + gc];
        rt = fminf(fmaxf(a * xi + b, 0.0f), 1.0f); rt = fmaxf(rt, 0.1f);
        yv = __fdividef(xi - avg, rt) + avg;
        out[2*HWT + row*WW + gc] = fminf(fmaxf(yv, 0.0f), 1.0f);
    }
}

// ---------------- launch ----------------
extern "C" void kernel_launch(void* const* d_in, const int* in_sizes, int n_in,
                              void* d_out, int out_size) {
    const float* x = (const float*)d_in[0];
    float* out = (float*)d_out;

    k_init<<<2048, 256>>>();
    k_cmin_hmin<<<dim3(8, 2048), 256>>>(x);
    k_vmin<<<dim3(8, 128), 256>>>();
    k_hist1<<<1024, 256>>>();
    k_scan1<<<1, 256>>>();
    k_hist2<<<1024, 256>>>();
    k_scan2<<<1, 1024>>>();
    k_mask<<<1024, 256>>>(x);
    k_avg<<<1, 1>>>();
    k_vpass<<<dim3(8, 32), 128>>>(x);
    k_hfinal<<<dim3(2, 2048), 256>>>(x, out);
}

// round 6
// speedup vs baseline: 2.2132x; 2.2132x over previous
#include <cuda_runtime.h>

#define HH 2048
#define WW 2048
#define HWT (HH*WW)
#define RD 7
#define RG 60
#define KSEL 4195u          /* (H*W)//1000 + 1 : rank of threshold (1-based from top) */
#define OMEGA 0.95f
#define EPSG 1e-4f

// ---------------- scratch (device globals; no allocation) ----------------
__device__ float    g_dch[HWT];            // horizontal-min intermediate
__device__ float    g_dc[HWT];             // dark channel
__device__ float    g_vsum[10*HWT];        // 10 vertically box-summed planes (160MB)
__device__ unsigned g_hist1[2048];         // coarse bins: float bits >> 19
__device__ unsigned g_hist2b[524288];      // fine bins: low 19 bits (within coarse bin)
__device__ unsigned g_chunk[1024];         // 512-bin chunk sums of g_hist2b
__device__ unsigned g_selKey;
__device__ unsigned g_selRank;
__device__ float    g_thres;
__device__ unsigned g_cnt;
__device__ float    g_sumr, g_sumg, g_sumb;
__device__ float    g_avg, g_invavg;

// ---------------- init: zero histograms / accumulators ----------------
__global__ void k_init() {
    int i = blockIdx.x * blockDim.x + threadIdx.x;
    if (i < 524288) g_hist2b[i] = 0u;
    if (i < 2048)   g_hist1[i]  = 0u;
    if (i < 1024)   g_chunk[i]  = 0u;
    if (i == 0) {
        g_cnt = 0u; g_sumr = 0.f; g_sumg = 0.f; g_sumb = 0.f;
        g_selKey = 0u; g_selRank = 0u; g_thres = 0.f;
    }
}

// ---------------- channel-min + horizontal min (r=7) ----------------
__global__ void __launch_bounds__(256) k_cmin_hmin(const float* __restrict__ x) {
    __shared__ float s[256 + 2*RD];
    int row = blockIdx.y;
    int x0  = blockIdx.x * 256;
    int t   = threadIdx.x;
    for (int i = t; i < 256 + 2*RD; i += 256) {
        int xx = x0 - RD + i;
        float v = 1e30f;
        if (xx >= 0 && xx < WW) {
            float r = x[0*HWT + row*WW + xx];
            float g = x[1*HWT + row*WW + xx];
            float b = x[2*HWT + row*WW + xx];
            v = fminf(r, fminf(g, b));
        }
        s[i] = v;
    }
    __syncthreads();
    float m = s[t];
#pragma unroll
    for (int j = 1; j <= 2*RD; j++) m = fminf(m, s[t + j]);
    g_dch[row*WW + x0 + t] = m;
}

// ---------------- vertical min (r=7) ----------------
__global__ void __launch_bounds__(256) k_vmin() {
    __shared__ float s[16 + 2*RD][256];
    int xx = blockIdx.x * 256 + threadIdx.x;
    int y0 = blockIdx.y * 16;
    for (int r = 0; r < 16 + 2*RD; r++) {
        int yy = y0 - RD + r;
        s[r][threadIdx.x] = (yy >= 0 && yy < HH) ? g_dch[yy*WW + xx] : 1e30f;
    }
    __syncthreads();
    for (int k = 0; k < 16; k++) {
        float m = s[k][threadIdx.x];
#pragma unroll
        for (int j = 1; j <= 2*RD; j++) m = fminf(m, s[k + j][threadIdx.x]);
        g_dc[(y0 + k)*WW + xx] = m;
    }
}

// ---------------- histogram pass 1: coarse bins (bits>>19), smem private ----------------
__global__ void __launch_bounds__(256) k_hist1() {
    __shared__ unsigned sh[2048];
    int t = threadIdx.x;
    for (int i = t; i < 2048; i += 256) sh[i] = 0u;
    __syncthreads();
    int tid = blockIdx.x * 256 + t;
    int stride = gridDim.x * 256;
    int lane = t & 31;
    for (int i = tid; i < HWT; i += stride) {
        unsigned key = __float_as_uint(g_dc[i]) >> 19;   // < 2048 for dc in [0,1)
        unsigned prev = __shfl_up_sync(0xffffffffu, key, 1);
        bool leader = (lane == 0) || (key != prev);
        unsigned bal = __ballot_sync(0xffffffffu, leader);
        if (leader) {
            unsigned above = (lane == 31) ? 0u : (bal >> (lane + 1));
            int run = above ? __ffs((int)above) : (32 - lane);
            atomicAdd(&sh[key], (unsigned)run);
        }
    }
    __syncthreads();
    for (int i = t; i < 2048; i += 256) {
        unsigned v = sh[i];
        if (v) atomicAdd(&g_hist1[i], v);
    }
}

// ---------------- find coarse bin containing the KSEL-th largest ----------------
__global__ void k_scan1() {
    __shared__ unsigned sh[2048];
    int t = threadIdx.x;
    for (int i = t; i < 2048; i += 256) sh[i] = g_hist1[i];
    __syncthreads();
    if (t == 0) {
        unsigned cum = 0;
        for (int j = 2047; j >= 0; j--) {
            unsigned h = sh[j];
            if (cum + h >= KSEL) {
                g_selKey = (unsigned)j;
                g_selRank = KSEL - cum;
                break;
            }
            cum += h;
        }
    }
}

// ---------------- histogram pass 2: low 19 bits within selected coarse bin ----------------
__global__ void k_hist2() {
    unsigned B = g_selKey;
    int tid = blockIdx.x * blockDim.x + threadIdx.x;
    int stride = gridDim.x * blockDim.x;
    for (int i = tid; i < HWT; i += stride) {
        unsigned bits = __float_as_uint(g_dc[i]);
        if ((bits >> 19) == B) atomicAdd(&g_hist2b[bits & 0x7FFFFu], 1u);
    }
}

// ---------------- reduce fine histogram into 1024 chunk sums (coalesced) ----------------
__global__ void __launch_bounds__(128) k_chunks() {
    __shared__ unsigned w[4];
    int b = blockIdx.x, t = threadIdx.x;
    unsigned s = 0;
#pragma unroll
    for (int k = 0; k < 4; k++) s += g_hist2b[b * 512 + k * 128 + t];
#pragma unroll
    for (int o = 16; o > 0; o >>= 1) s += __shfl_down_sync(0xffffffffu, s, o);
    if ((t & 31) == 0) w[t >> 5] = s;
    __syncthreads();
    if (t == 0) g_chunk[b] = w[0] + w[1] + w[2] + w[3];
}

// ---------------- select chunk, then exact fine bin ----------------
__global__ void __launch_bounds__(1024) k_scan2() {
    __shared__ unsigned sc[1024];
    __shared__ unsigned sb[512];
    __shared__ int selC;
    __shared__ unsigned selR;
    unsigned K = g_selRank;
    int t = threadIdx.x;
    sc[t] = g_chunk[t];                     // coalesced
    __syncthreads();
    if (t == 0) {
        unsigned cum = 0;
        for (int j = 1023; j >= 0; j--) {
            unsigned h = sc[j];
            if (cum + h >= K) { selC = j; selR = K - cum; break; }
            cum += h;
        }
    }
    __syncthreads();
    int c = selC;
    if (t < 512) sb[t] = g_hist2b[c * 512 + t];   // coalesced
    __syncthreads();
    if (t == 0) {
        unsigned K2 = selR;
        unsigned cum = 0;
        for (int j = 511; j >= 0; j--) {
            unsigned h = sb[j];
            if (cum + h >= K2) {
                g_thres = __uint_as_float((g_selKey << 19) | (unsigned)(c * 512 + j));
                break;
            }
            cum += h;
        }
    }
}

// ---------------- masked sums for atmospheric light ----------------
__global__ void k_mask(const float* __restrict__ x) {
    float th = g_thres;
    int tid = blockIdx.x * blockDim.x + threadIdx.x;
    int stride = gridDim.x * blockDim.x;
    unsigned cnt = 0; float sr = 0.f, sg = 0.f, sb = 0.f;
    for (int i = tid; i < HWT; i += stride) {
        if (g_dc[i] >= th) {
            cnt++;
            sr += x[i];
            sg += x[HWT + i];
            sb += x[2*HWT + i];
        }
    }
#pragma unroll
    for (int o = 16; o > 0; o >>= 1) {
        cnt += __shfl_down_sync(0xffffffffu, cnt, o);
        sr  += __shfl_down_sync(0xffffffffu, sr,  o);
        sg  += __shfl_down_sync(0xffffffffu, sg,  o);
        sb  += __shfl_down_sync(0xffffffffu, sb,  o);
    }
    if ((threadIdx.x & 31) == 0) {
        atomicAdd(&g_cnt, cnt);
        atomicAdd(&g_sumr, sr);
        atomicAdd(&g_sumg, sg);
        atomicAdd(&g_sumb, sb);
    }
}

__global__ void k_avg() {
    float c = (float)g_cnt;
    float avg = (0.299f * g_sumr + 0.587f * g_sumg + 0.114f * g_sumb) / c;
    g_avg = avg;
    g_invavg = 1.0f / avg;
}

// ---------------- one row's 10 plane values (scalar per thread) ----------------
__device__ __forceinline__ void vrow(const float* __restrict__ x, int yy, int c,
                                     float inva, float v[10]) {
    float a0 = x[0*HWT + yy*WW + c];
    float a1 = x[1*HWT + yy*WW + c];
    float a2 = x[2*HWT + yy*WW + c];
    float d  = g_dc[yy*WW + c];
    float p = fmaf(-OMEGA * inva, d, 1.0f);
    v[0] = p;
    v[1] = a0; v[2] = a1; v[3] = a2;
    v[4] = p * a0; v[5] = p * a1; v[6] = p * a2;
    v[7] = a0 * a0; v[8] = a1 * a1; v[9] = a2 * a2;
}

// ---------------- vertical rolling box sums of the 10 planes ----------------
__global__ void __launch_bounds__(256) k_vpass(const float* __restrict__ x) {
    const int S = 64;
    int c  = blockIdx.x * 256 + threadIdx.x;
    int y0 = blockIdx.y * S;
    float inva = g_invavg;
    float s[10];
#pragma unroll
    for (int p = 0; p < 10; p++) s[p] = 0.f;

    int ylo = y0 - RG; if (ylo < 0) ylo = 0;
    int yhi = y0 + RG; if (yhi > HH - 1) yhi = HH - 1;
#pragma unroll 4
    for (int yy = ylo; yy <= yhi; yy++) {
        float v[10];
        vrow(x, yy, c, inva, v);
#pragma unroll
        for (int p = 0; p < 10; p++) s[p] += v[p];
    }
    for (int k = 0; k < S; k++) {
        int y = y0 + k;
        if (k > 0) {
            int ya = y + RG;
            if (ya < HH) {
                float v[10];
                vrow(x, ya, c, inva, v);
#pragma unroll
                for (int p = 0; p < 10; p++) s[p] += v[p];
            }
            int yr = y - RG - 1;
            if (yr >= 0) {
                float v[10];
                vrow(x, yr, c, inva, v);
#pragma unroll
                for (int p = 0; p < 10; p++) s[p] -= v[p];
            }
        }
#pragma unroll
        for (int p = 0; p < 10; p++)
            g_vsum[p*HWT + y*WW + c] = s[p];
    }
}

// ---------------- horizontal box sums (block scans, 2 planes/round) + epilogue ----------------
// one block per half-row: 1024 output cols + 60-col halo each side, zero-padded
#define SEG 1144
__global__ void __launch_bounds__(256) k_hfinal(const float* __restrict__ x,
                                                float* __restrict__ out) {
    __shared__ float sps[10][SEG];
    __shared__ float2 wpart[8];
    int row = blockIdx.y;
    int c0  = blockIdx.x * 1024;
    int s0  = c0 - RG;
    int t = threadIdx.x, lane = t & 31, wid = t >> 5;

    for (int pl = 0; pl < 10; pl += 2) {
        const float* __restrict__ srcA = g_vsum + (pl+0)*HWT + row*WW;
        const float* __restrict__ srcB = g_vsum + (pl+1)*HWT + row*WW;
        float carryA = 0.f, carryB = 0.f;
        for (int ch = 0; ch < 5; ch++) {
            int L = ch * 256 + t;
            int gc = s0 + L;
            float vA = 0.f, vB = 0.f;
            bool in = (L < SEG && gc >= 0 && gc < WW);
            if (in) { vA = srcA[gc]; vB = srcB[gc]; }
            float scA = vA, scB = vB;
#pragma unroll
            for (int o = 1; o < 32; o <<= 1) {
                float nA = __shfl_up_sync(0xffffffffu, scA, o);
                float nB = __shfl_up_sync(0xffffffffu, scB, o);
                if (lane >= o) { scA += nA; scB += nB; }
            }
            if (lane == 31) wpart[wid] = make_float2(scA, scB);
            __syncthreads();
            float offA = carryA, offB = carryB, totA = 0.f, totB = 0.f;
#pragma unroll
            for (int w = 0; w < 8; w++) {
                float2 pw = wpart[w];
                totA += pw.x; totB += pw.y;
                if (w < wid) { offA += pw.x; offB += pw.y; }
            }
            if (L < SEG) {
                sps[pl+0][L] = scA + offA;
                sps[pl+1][L] = scB + offB;
            }
            carryA += totA; carryB += totB;
            __syncthreads();
        }
    }

    float avg = g_avg;
    int ny = min(row + RG, HH - 1) - max(row - RG, 0) + 1;
#pragma unroll
    for (int j = 0; j < 4; j++) {
        int L = t + j * 256;          // 0..1023
        int gc = c0 + L;
        int hi = L + 2*RG;            // local index of gc+RG
        int lo = L - 1;               // local index of gc-RG-1
        float w0 = sps[0][hi] - (lo >= 0 ? sps[0][lo] : 0.f);
        float w1 = sps[1][hi] - (lo >= 0 ? sps[1][lo] : 0.f);
        float w2 = sps[2][hi] - (lo >= 0 ? sps[2][lo] : 0.f);
        float w3 = sps[3][hi] - (lo >= 0 ? sps[3][lo] : 0.f);
        float w4 = sps[4][hi] - (lo >= 0 ? sps[4][lo] : 0.f);
        float w5 = sps[5][hi] - (lo >= 0 ? sps[5][lo] : 0.f);
        float w6 = sps[6][hi] - (lo >= 0 ? sps[6][lo] : 0.f);
        float w7 = sps[7][hi] - (lo >= 0 ? sps[7][lo] : 0.f);
        float w8 = sps[8][hi] - (lo >= 0 ? sps[8][lo] : 0.f);
        float w9 = sps[9][hi] - (lo >= 0 ? sps[9][lo] : 0.f);
        int nx = min(gc + RG, WW - 1) - max(gc - RG, 0) + 1;
        float invN = __fdividef(1.0f, (float)(nx * ny));
        float mp = w0 * invN;
        float mi, mpi, mii, cip, cii, a, b, xi, rt, yv;
        // ch 0
        mi = w1 * invN; mpi = w4 * invN; mii = w7 * invN;
        cip = mpi - mp * mi; cii = mii - mi * mi;
        a = __fdividef(cip, cii + EPSG); b = mp - a * mi;
        xi = x[0*HWT + row*WW + gc];
        rt = fminf(fmaxf(a * xi + b, 0.0f), 1.0f); rt = fmaxf(rt, 0.1f);
        yv = __fdividef(xi - avg, rt) + avg;
        out[0*HWT + row*WW + gc] = fminf(fmaxf(yv, 0.0f), 1.0f);
        // ch 1
        mi = w2 * invN; mpi = w5 * invN; mii = w8 * invN;
        cip = mpi - mp * mi; cii = mii - mi * mi;
        a = __fdividef(cip, cii + EPSG); b = mp - a * mi;
        xi = x[1*HWT + row*WW + gc];
        rt = fminf(fmaxf(a * xi + b, 0.0f), 1.0f); rt = fmaxf(rt, 0.1f);
        yv = __fdividef(xi - avg, rt) + avg;
        out[1*HWT + row*WW + gc] = fminf(fmaxf(yv, 0.0f), 1.0f);
        // ch 2
        mi = w3 * invN; mpi = w6 * invN; mii = w9 * invN;
        cip = mpi - mp * mi; cii = mii - mi * mi;
        a = __fdividef(cip, cii + EPSG); b = mp - a * mi;
        xi = x[2*HWT + row*WW + gc];
        rt = fminf(fmaxf(a * xi + b, 0.0f), 1.0f); rt = fmaxf(rt, 0.1f);
        yv = __fdividef(xi - avg, rt) + avg;
        out[2*HWT + row*WW + gc] = fminf(fmaxf(yv, 0.0f), 1.0f);
    }
}

// ---------------- launch ----------------
extern "C" void kernel_launch(void* const* d_in, const int* in_sizes, int n_in,
                              void* d_out, int out_size) {
    const float* x = (const float*)d_in[0];
    float* out = (float*)d_out;

    k_init<<<2048, 256>>>();
    k_cmin_hmin<<<dim3(8, 2048), 256>>>(x);
    k_vmin<<<dim3(8, 128), 256>>>();
    k_hist1<<<1024, 256>>>();
    k_scan1<<<1, 256>>>();
    k_hist2<<<1024, 256>>>();
    k_chunks<<<1024, 128>>>();
    k_scan2<<<1, 1024>>>();
    k_mask<<<1024, 256>>>(x);
    k_avg<<<1, 1>>>();
    k_vpass<<<dim3(8, 32), 256>>>(x);
    k_hfinal<<<dim3(2, 2048), 256>>>(x, out);
}

// round 7
// speedup vs baseline: 2.5532x; 1.1536x over previous
#include <cuda_runtime.h>

#define HH 2048
#define WW 2048
#define HWT (HH*WW)
#define RD 7
#define RG 60
#define KSEL 4195u          /* (H*W)//1000 + 1 : rank of threshold (1-based from top) */
#define OMEGA 0.95f
#define EPSG 1e-4f

// ---------------- scratch (device globals; no allocation) ----------------
__device__ float    g_dch[HWT];            // horizontal-min intermediate
__device__ float    g_dc[HWT];             // dark channel
__device__ float    g_vsum[10*HWT];        // 10 vertically box-summed planes (160MB)
__device__ unsigned g_hist1[2048];         // coarse bins: float bits >> 19
__device__ unsigned g_hist2b[524288];      // fine bins: low 19 bits (within coarse bin)
__device__ unsigned g_chunk[1024];         // 512-bin chunk sums of g_hist2b
__device__ unsigned g_selKey;
__device__ unsigned g_selRank;
__device__ float    g_thres;
__device__ unsigned g_cnt;
__device__ float    g_sumr, g_sumg, g_sumb;
__device__ float    g_avg, g_invavg;

// ---------------- init: zero histograms / accumulators ----------------
__global__ void k_init() {
    int i = blockIdx.x * blockDim.x + threadIdx.x;
    if (i < 524288) g_hist2b[i] = 0u;
    if (i < 2048)   g_hist1[i]  = 0u;
    if (i < 1024)   g_chunk[i]  = 0u;
    if (i == 0) {
        g_cnt = 0u; g_sumr = 0.f; g_sumg = 0.f; g_sumb = 0.f;
        g_selKey = 0u; g_selRank = 0u; g_thres = 0.f;
    }
}

// ---------------- channel-min + horizontal min (r=7) ----------------
__global__ void __launch_bounds__(256) k_cmin_hmin(const float* __restrict__ x) {
    __shared__ float s[256 + 2*RD];
    int row = blockIdx.y;
    int x0  = blockIdx.x * 256;
    int t   = threadIdx.x;
    for (int i = t; i < 256 + 2*RD; i += 256) {
        int xx = x0 - RD + i;
        float v = 1e30f;
        if (xx >= 0 && xx < WW) {
            float r = x[0*HWT + row*WW + xx];
            float g = x[1*HWT + row*WW + xx];
            float b = x[2*HWT + row*WW + xx];
            v = fminf(r, fminf(g, b));
        }
        s[i] = v;
    }
    __syncthreads();
    float m = s[t];
#pragma unroll
    for (int j = 1; j <= 2*RD; j++) m = fminf(m, s[t + j]);
    g_dch[row*WW + x0 + t] = m;
}

// ---------------- vertical min (r=7) ----------------
__global__ void __launch_bounds__(256) k_vmin() {
    __shared__ float s[16 + 2*RD][256];
    int xx = blockIdx.x * 256 + threadIdx.x;
    int y0 = blockIdx.y * 16;
    for (int r = 0; r < 16 + 2*RD; r++) {
        int yy = y0 - RD + r;
        s[r][threadIdx.x] = (yy >= 0 && yy < HH) ? g_dch[yy*WW + xx] : 1e30f;
    }
    __syncthreads();
    for (int k = 0; k < 16; k++) {
        float m = s[k][threadIdx.x];
#pragma unroll
        for (int j = 1; j <= 2*RD; j++) m = fminf(m, s[k + j][threadIdx.x]);
        g_dc[(y0 + k)*WW + xx] = m;
    }
}

// ---------------- histogram pass 1: coarse bins (bits>>19), smem private ----------------
__global__ void __launch_bounds__(256) k_hist1() {
    __shared__ unsigned sh[2048];
    int t = threadIdx.x;
    for (int i = t; i < 2048; i += 256) sh[i] = 0u;
    __syncthreads();
    int tid = blockIdx.x * 256 + t;
    int stride = gridDim.x * 256;
    int lane = t & 31;
    for (int i = tid; i < HWT; i += stride) {
        unsigned key = __float_as_uint(g_dc[i]) >> 19;   // < 2048 for dc in [0,1)
        unsigned prev = __shfl_up_sync(0xffffffffu, key, 1);
        bool leader = (lane == 0) || (key != prev);
        unsigned bal = __ballot_sync(0xffffffffu, leader);
        if (leader) {
            unsigned above = (lane == 31) ? 0u : (bal >> (lane + 1));
            int run = above ? __ffs((int)above) : (32 - lane);
            atomicAdd(&sh[key], (unsigned)run);
        }
    }
    __syncthreads();
    for (int i = t; i < 2048; i += 256) {
        unsigned v = sh[i];
        if (v) atomicAdd(&g_hist1[i], v);
    }
}

// ---------------- find coarse bin containing the KSEL-th largest ----------------
__global__ void k_scan1() {
    __shared__ unsigned sh[2048];
    int t = threadIdx.x;
    for (int i = t; i < 2048; i += 256) sh[i] = g_hist1[i];
    __syncthreads();
    if (t == 0) {
        unsigned cum = 0;
        for (int j = 2047; j >= 0; j--) {
            unsigned h = sh[j];
            if (cum + h >= KSEL) {
                g_selKey = (unsigned)j;
                g_selRank = KSEL - cum;
                break;
            }
            cum += h;
        }
    }
}

// ---------------- histogram pass 2: low 19 bits within selected coarse bin ----------------
__global__ void k_hist2() {
    unsigned B = g_selKey;
    int tid = blockIdx.x * blockDim.x + threadIdx.x;
    int stride = gridDim.x * blockDim.x;
    for (int i = tid; i < HWT; i += stride) {
        unsigned bits = __float_as_uint(g_dc[i]);
        if ((bits >> 19) == B) atomicAdd(&g_hist2b[bits & 0x7FFFFu], 1u);
    }
}

// ---------------- reduce fine histogram into 1024 chunk sums (coalesced) ----------------
__global__ void __launch_bounds__(128) k_chunks() {
    __shared__ unsigned w[4];
    int b = blockIdx.x, t = threadIdx.x;
    unsigned s = 0;
#pragma unroll
    for (int k = 0; k < 4; k++) s += g_hist2b[b * 512 + k * 128 + t];
#pragma unroll
    for (int o = 16; o > 0; o >>= 1) s += __shfl_down_sync(0xffffffffu, s, o);
    if ((t & 31) == 0) w[t >> 5] = s;
    __syncthreads();
    if (t == 0) g_chunk[b] = w[0] + w[1] + w[2] + w[3];
}

// ---------------- select chunk, then exact fine bin ----------------
__global__ void __launch_bounds__(1024) k_scan2() {
    __shared__ unsigned sc[1024];
    __shared__ unsigned sb[512];
    __shared__ int selC;
    __shared__ unsigned selR;
    unsigned K = g_selRank;
    int t = threadIdx.x;
    sc[t] = g_chunk[t];                     // coalesced
    __syncthreads();
    if (t == 0) {
        unsigned cum = 0;
        for (int j = 1023; j >= 0; j--) {
            unsigned h = sc[j];
            if (cum + h >= K) { selC = j; selR = K - cum; break; }
            cum += h;
        }
    }
    __syncthreads();
    int c = selC;
    if (t < 512) sb[t] = g_hist2b[c * 512 + t];   // coalesced
    __syncthreads();
    if (t == 0) {
        unsigned K2 = selR;
        unsigned cum = 0;
        for (int j = 511; j >= 0; j--) {
            unsigned h = sb[j];
            if (cum + h >= K2) {
                g_thres = __uint_as_float((g_selKey << 19) | (unsigned)(c * 512 + j));
                break;
            }
            cum += h;
        }
    }
}

// ---------------- masked sums for atmospheric light ----------------
__global__ void k_mask(const float* __restrict__ x) {
    float th = g_thres;
    int tid = blockIdx.x * blockDim.x + threadIdx.x;
    int stride = gridDim.x * blockDim.x;
    unsigned cnt = 0; float sr = 0.f, sg = 0.f, sb = 0.f;
    for (int i = tid; i < HWT; i += stride) {
        if (g_dc[i] >= th) {
            cnt++;
            sr += x[i];
            sg += x[HWT + i];
            sb += x[2*HWT + i];
        }
    }
#pragma unroll
    for (int o = 16; o > 0; o >>= 1) {
        cnt += __shfl_down_sync(0xffffffffu, cnt, o);
        sr  += __shfl_down_sync(0xffffffffu, sr,  o);
        sg  += __shfl_down_sync(0xffffffffu, sg,  o);
        sb  += __shfl_down_sync(0xffffffffu, sb,  o);
    }
    if ((threadIdx.x & 31) == 0) {
        atomicAdd(&g_cnt, cnt);
        atomicAdd(&g_sumr, sr);
        atomicAdd(&g_sumg, sg);
        atomicAdd(&g_sumb, sb);
    }
}

__global__ void k_avg() {
    float c = (float)g_cnt;
    float avg = (0.299f * g_sumr + 0.587f * g_sumg + 0.114f * g_sumb) / c;
    g_avg = avg;
    g_invavg = 1.0f / avg;
}

// ---------------- one row's 10 plane values (scalar per thread) ----------------
__device__ __forceinline__ void vrow(const float* __restrict__ x, int yy, int c,
                                     float inva, float v[10]) {
    float a0 = x[0*HWT + yy*WW + c];
    float a1 = x[1*HWT + yy*WW + c];
    float a2 = x[2*HWT + yy*WW + c];
    float d  = g_dc[yy*WW + c];
    float p = fmaf(-OMEGA * inva, d, 1.0f);
    v[0] = p;
    v[1] = a0; v[2] = a1; v[3] = a2;
    v[4] = p * a0; v[5] = p * a1; v[6] = p * a2;
    v[7] = a0 * a0; v[8] = a1 * a1; v[9] = a2 * a2;
}

// ---------------- vertical rolling box sums of the 10 planes ----------------
#define VS 32
__global__ void __launch_bounds__(256) k_vpass(const float* __restrict__ x) {
    int c  = blockIdx.x * 256 + threadIdx.x;
    int y0 = blockIdx.y * VS;
    float inva = g_invavg;
    float s[10];
#pragma unroll
    for (int p = 0; p < 10; p++) s[p] = 0.f;

    bool interior = (y0 >= RG + 1) && (y0 + VS - 1 + RG < HH);

    int ylo = y0 - RG; if (ylo < 0) ylo = 0;
    int yhi = y0 + RG; if (yhi > HH - 1) yhi = HH - 1;
#pragma unroll 4
    for (int yy = ylo; yy <= yhi; yy++) {
        float v[10];
        vrow(x, yy, c, inva, v);
#pragma unroll
        for (int p = 0; p < 10; p++) s[p] += v[p];
    }

    if (interior) {
#pragma unroll
        for (int p = 0; p < 10; p++)
            g_vsum[p*HWT + y0*WW + c] = s[p];
#pragma unroll 2
        for (int k = 1; k < VS; k++) {
            int y = y0 + k;
            float va[10], vs[10];
            vrow(x, y + RG, c, inva, va);
            vrow(x, y - RG - 1, c, inva, vs);
#pragma unroll
            for (int p = 0; p < 10; p++) s[p] += va[p] - vs[p];
#pragma unroll
            for (int p = 0; p < 10; p++)
                g_vsum[p*HWT + y*WW + c] = s[p];
        }
    } else {
        for (int k = 0; k < VS; k++) {
            int y = y0 + k;
            if (k > 0) {
                int ya = y + RG;
                if (ya < HH) {
                    float v[10];
                    vrow(x, ya, c, inva, v);
#pragma unroll
                    for (int p = 0; p < 10; p++) s[p] += v[p];
                }
                int yr = y - RG - 1;
                if (yr >= 0) {
                    float v[10];
                    vrow(x, yr, c, inva, v);
#pragma unroll
                    for (int p = 0; p < 10; p++) s[p] -= v[p];
                }
            }
#pragma unroll
            for (int p = 0; p < 10; p++)
                g_vsum[p*HWT + y*WW + c] = s[p];
        }
    }
}

// ---------------- horizontal box sums (block scans, 2 planes/round) + epilogue ----------------
// one block per half-row: 1024 output cols + 60-col halo each side, zero-padded
#define SEG 1144
__global__ void __launch_bounds__(256) k_hfinal(const float* __restrict__ x,
                                                float* __restrict__ out) {
    __shared__ float sps[10][SEG];
    __shared__ float2 wpart[8];
    int row = blockIdx.y;
    int c0  = blockIdx.x * 1024;
    int s0  = c0 - RG;
    int t = threadIdx.x, lane = t & 31, wid = t >> 5;

    for (int pl = 0; pl < 10; pl += 2) {
        const float* __restrict__ srcA = g_vsum + (pl+0)*HWT + row*WW;
        const float* __restrict__ srcB = g_vsum + (pl+1)*HWT + row*WW;
        float carryA = 0.f, carryB = 0.f;
        for (int ch = 0; ch < 5; ch++) {
            int L = ch * 256 + t;
            int gc = s0 + L;
            float vA = 0.f, vB = 0.f;
            bool in = (L < SEG && gc >= 0 && gc < WW);
            if (in) { vA = srcA[gc]; vB = srcB[gc]; }
            float scA = vA, scB = vB;
#pragma unroll
            for (int o = 1; o < 32; o <<= 1) {
                float nA = __shfl_up_sync(0xffffffffu, scA, o);
                float nB = __shfl_up_sync(0xffffffffu, scB, o);
                if (lane >= o) { scA += nA; scB += nB; }
            }
            if (lane == 31) wpart[wid] = make_float2(scA, scB);
            __syncthreads();
            float offA = carryA, offB = carryB, totA = 0.f, totB = 0.f;
#pragma unroll
            for (int w = 0; w < 8; w++) {
                float2 pw = wpart[w];
                totA += pw.x; totB += pw.y;
                if (w < wid) { offA += pw.x; offB += pw.y; }
            }
            if (L < SEG) {
                sps[pl+0][L] = scA + offA;
                sps[pl+1][L] = scB + offB;
            }
            carryA += totA; carryB += totB;
            __syncthreads();
        }
    }

    float avg = g_avg;
    int ny = min(row + RG, HH - 1) - max(row - RG, 0) + 1;
#pragma unroll
    for (int j = 0; j < 4; j++) {
        int L = t + j * 256;          // 0..1023
        int gc = c0 + L;
        int hi = L + 2*RG;            // local index of gc+RG
        int lo = L - 1;               // local index of gc-RG-1
        float w0 = sps[0][hi] - (lo >= 0 ? sps[0][lo] : 0.f);
        float w1 = sps[1][hi] - (lo >= 0 ? sps[1][lo] : 0.f);
        float w2 = sps[2][hi] - (lo >= 0 ? sps[2][lo] : 0.f);
        float w3 = sps[3][hi] - (lo >= 0 ? sps[3][lo] : 0.f);
        float w4 = sps[4][hi] - (lo >= 0 ? sps[4][lo] : 0.f);
        float w5 = sps[5][hi] - (lo >= 0 ? sps[5][lo] : 0.f);
        float w6 = sps[6][hi] - (lo >= 0 ? sps[6][lo] : 0.f);
        float w7 = sps[7][hi] - (lo >= 0 ? sps[7][lo] : 0.f);
        float w8 = sps[8][hi] - (lo >= 0 ? sps[8][lo] : 0.f);
        float w9 = sps[9][hi] - (lo >= 0 ? sps[9][lo] : 0.f);
        int nx = min(gc + RG, WW - 1) - max(gc - RG, 0) + 1;
        float invN = __fdividef(1.0f, (float)(nx * ny));
        float mp = w0 * invN;
        float mi, mpi, mii, cip, cii, a, b, xi, rt, yv;
        // ch 0
        mi = w1 * invN; mpi = w4 * invN; mii = w7 * invN;
        cip = mpi - mp * mi; cii = mii - mi * mi;
        a = __fdividef(cip, cii + EPSG); b = mp - a * mi;
        xi = x[0*HWT + row*WW + gc];
        rt = fminf(fmaxf(a * xi + b, 0.0f), 1.0f); rt = fmaxf(rt, 0.1f);
        yv = __fdividef(xi - avg, rt) + avg;
        out[0*HWT + row*WW + gc] = fminf(fmaxf(yv, 0.0f), 1.0f);
        // ch 1
        mi = w2 * invN; mpi = w5 * invN; mii = w8 * invN;
        cip = mpi - mp * mi; cii = mii - mi * mi;
        a = __fdividef(cip, cii + EPSG); b = mp - a * mi;
        xi = x[1*HWT + row*WW + gc];
        rt = fminf(fmaxf(a * xi + b, 0.0f), 1.0f); rt = fmaxf(rt, 0.1f);
        yv = __fdividef(xi - avg, rt) + avg;
        out[1*HWT + row*WW + gc] = fminf(fmaxf(yv, 0.0f), 1.0f);
        // ch 2
        mi = w3 * invN; mpi = w6 * invN; mii = w9 * invN;
        cip = mpi - mp * mi; cii = mii - mi * mi;
        a = __fdividef(cip, cii + EPSG); b = mp - a * mi;
        xi = x[2*HWT + row*WW + gc];
        rt = fminf(fmaxf(a * xi + b, 0.0f), 1.0f); rt = fmaxf(rt, 0.1f);
        yv = __fdividef(xi - avg, rt) + avg;
        out[2*HWT + row*WW + gc] = fminf(fmaxf(yv, 0.0f), 1.0f);
    }
}

// ---------------- launch ----------------
extern "C" void kernel_launch(void* const* d_in, const int* in_sizes, int n_in,
                              void* d_out, int out_size) {
    const float* x = (const float*)d_in[0];
    float* out = (float*)d_out;

    k_init<<<2048, 256>>>();
    k_cmin_hmin<<<dim3(8, 2048), 256>>>(x);
    k_vmin<<<dim3(8, 128), 256>>>();
    k_hist1<<<1024, 256>>>();
    k_scan1<<<1, 256>>>();
    k_hist2<<<1024, 256>>>();
    k_chunks<<<1024, 128>>>();
    k_scan2<<<1, 1024>>>();
    k_mask<<<1024, 256>>>(x);
    k_avg<<<1, 1>>>();
    k_vpass<<<dim3(8, 64), 256>>>(x);
    k_hfinal<<<dim3(2, 2048), 256>>>(x, out);
}

// round 8
// speedup vs baseline: 2.5688x; 1.0061x over previous
#include <cuda_runtime.h>

#define HH 2048
#define WW 2048
#define HWT (HH*WW)
#define RD 7
#define RG 60
#define KSEL 4195u          /* (H*W)//1000 + 1 : rank of threshold (1-based from top) */
#define OMEGA 0.95f
#define EPSG 1e-4f

// ---------------- scratch (device globals; no allocation) ----------------
__device__ float    g_dch[HWT];            // horizontal-min intermediate
__device__ float    g_dc[HWT];             // dark channel
__device__ float    g_vsum[10*HWT];        // 10 vertically box-summed planes (160MB)
__device__ unsigned g_hist1[2048];         // coarse bins: float bits >> 19
__device__ unsigned g_hist2b[524288];      // fine bins: low 19 bits (within coarse bin)
__device__ unsigned g_chunk[1024];         // 512-bin chunk sums of g_hist2b
__device__ unsigned g_selKey;
__device__ unsigned g_selRank;
__device__ float    g_thres;
__device__ unsigned g_cnt;
__device__ float    g_sumr, g_sumg, g_sumb;
__device__ float    g_avg, g_invavg;

// ---------------- init: zero histograms / accumulators ----------------
__global__ void k_init() {
    int i = blockIdx.x * blockDim.x + threadIdx.x;
    if (i < 524288) g_hist2b[i] = 0u;
    if (i < 2048)   g_hist1[i]  = 0u;
    if (i < 1024)   g_chunk[i]  = 0u;
    if (i == 0) {
        g_cnt = 0u; g_sumr = 0.f; g_sumg = 0.f; g_sumb = 0.f;
        g_selKey = 0u; g_selRank = 0u; g_thres = 0.f;
    }
}

// ---------------- channel-min + horizontal min (r=7) ----------------
__global__ void __launch_bounds__(256) k_cmin_hmin(const float* __restrict__ x) {
    __shared__ float s[256 + 2*RD];
    int row = blockIdx.y;
    int x0  = blockIdx.x * 256;
    int t   = threadIdx.x;
    for (int i = t; i < 256 + 2*RD; i += 256) {
        int xx = x0 - RD + i;
        float v = 1e30f;
        if (xx >= 0 && xx < WW) {
            float r = x[0*HWT + row*WW + xx];
            float g = x[1*HWT + row*WW + xx];
            float b = x[2*HWT + row*WW + xx];
            v = fminf(r, fminf(g, b));
        }
        s[i] = v;
    }
    __syncthreads();
    float m = s[t];
#pragma unroll
    for (int j = 1; j <= 2*RD; j++) m = fminf(m, s[t + j]);
    g_dch[row*WW + x0 + t] = m;
}

// ---------------- vertical min (r=7) + fused coarse histogram ----------------
__global__ void __launch_bounds__(256) k_vmin_hist() {
    __shared__ float s[16 + 2*RD][256];
    __shared__ unsigned sh[2048];
    int t = threadIdx.x;
    for (int i = t; i < 2048; i += 256) sh[i] = 0u;
    int xx = blockIdx.x * 256 + t;
    int y0 = blockIdx.y * 16;
    for (int r = 0; r < 16 + 2*RD; r++) {
        int yy = y0 - RD + r;
        s[r][t] = (yy >= 0 && yy < HH) ? g_dch[yy*WW + xx] : 1e30f;
    }
    __syncthreads();
    int lane = t & 31;
    for (int k = 0; k < 16; k++) {
        float m = s[k][t];
#pragma unroll
        for (int j = 1; j <= 2*RD; j++) m = fminf(m, s[k + j][t]);
        g_dc[(y0 + k)*WW + xx] = m;
        unsigned key = __float_as_uint(m) >> 19;   // < 2048 for dc in [0,1)
        unsigned prev = __shfl_up_sync(0xffffffffu, key, 1);
        bool leader = (lane == 0) || (key != prev);
        unsigned bal = __ballot_sync(0xffffffffu, leader);
        if (leader) {
            unsigned above = (lane == 31) ? 0u : (bal >> (lane + 1));
            int run = above ? __ffs((int)above) : (32 - lane);
            atomicAdd(&sh[key], (unsigned)run);
        }
    }
    __syncthreads();
    for (int i = t; i < 2048; i += 256) {
        unsigned v = sh[i];
        if (v) atomicAdd(&g_hist1[i], v);
    }
}

// ---------------- find coarse bin containing the KSEL-th largest ----------------
__global__ void k_scan1() {
    __shared__ unsigned sh[2048];
    int t = threadIdx.x;
    for (int i = t; i < 2048; i += 256) sh[i] = g_hist1[i];
    __syncthreads();
    if (t == 0) {
        unsigned cum = 0;
        for (int j = 2047; j >= 0; j--) {
            unsigned h = sh[j];
            if (cum + h >= KSEL) {
                g_selKey = (unsigned)j;
                g_selRank = KSEL - cum;
                break;
            }
            cum += h;
        }
    }
}

// ---------------- histogram pass 2: low 19 bits within selected bin (uint4) ----------------
__global__ void k_hist2() {
    unsigned B = g_selKey;
    const uint4* __restrict__ dc4 = reinterpret_cast<const uint4*>(g_dc);
    int tid = blockIdx.x * blockDim.x + threadIdx.x;
    int stride = gridDim.x * blockDim.x;
    for (int i = tid; i < HWT/4; i += stride) {
        uint4 v = dc4[i];
        if ((v.x >> 19) == B) atomicAdd(&g_hist2b[v.x & 0x7FFFFu], 1u);
        if ((v.y >> 19) == B) atomicAdd(&g_hist2b[v.y & 0x7FFFFu], 1u);
        if ((v.z >> 19) == B) atomicAdd(&g_hist2b[v.z & 0x7FFFFu], 1u);
        if ((v.w >> 19) == B) atomicAdd(&g_hist2b[v.w & 0x7FFFFu], 1u);
    }
}

// ---------------- reduce fine histogram into 1024 chunk sums (coalesced) ----------------
__global__ void __launch_bounds__(128) k_chunks() {
    __shared__ unsigned w[4];
    int b = blockIdx.x, t = threadIdx.x;
    unsigned s = 0;
#pragma unroll
    for (int k = 0; k < 4; k++) s += g_hist2b[b * 512 + k * 128 + t];
#pragma unroll
    for (int o = 16; o > 0; o >>= 1) s += __shfl_down_sync(0xffffffffu, s, o);
    if ((t & 31) == 0) w[t >> 5] = s;
    __syncthreads();
    if (t == 0) g_chunk[b] = w[0] + w[1] + w[2] + w[3];
}

// ---------------- select chunk, then exact fine bin ----------------
__global__ void __launch_bounds__(1024) k_scan2() {
    __shared__ unsigned sc[1024];
    __shared__ unsigned sb[512];
    __shared__ int selC;
    __shared__ unsigned selR;
    unsigned K = g_selRank;
    int t = threadIdx.x;
    sc[t] = g_chunk[t];                     // coalesced
    __syncthreads();
    if (t == 0) {
        unsigned cum = 0;
        for (int j = 1023; j >= 0; j--) {
            unsigned h = sc[j];
            if (cum + h >= K) { selC = j; selR = K - cum; break; }
            cum += h;
        }
    }
    __syncthreads();
    int c = selC;
    if (t < 512) sb[t] = g_hist2b[c * 512 + t];   // coalesced
    __syncthreads();
    if (t == 0) {
        unsigned K2 = selR;
        unsigned cum = 0;
        for (int j = 511; j >= 0; j--) {
            unsigned h = sb[j];
            if (cum + h >= K2) {
                g_thres = __uint_as_float((g_selKey << 19) | (unsigned)(c * 512 + j));
                break;
            }
            cum += h;
        }
    }
}

// ---------------- masked sums for atmospheric light (float4 dc) ----------------
__global__ void k_mask(const float* __restrict__ x) {
    float th = g_thres;
    const float4* __restrict__ dc4 = reinterpret_cast<const float4*>(g_dc);
    int tid = blockIdx.x * blockDim.x + threadIdx.x;
    int stride = gridDim.x * blockDim.x;
    unsigned cnt = 0; float sr = 0.f, sg = 0.f, sb = 0.f;
    for (int i = tid; i < HWT/4; i += stride) {
        float4 d = dc4[i];
        int base = i * 4;
#pragma unroll
        for (int j = 0; j < 4; j++) {
            float dv = (j == 0) ? d.x : (j == 1) ? d.y : (j == 2) ? d.z : d.w;
            if (dv >= th) {
                cnt++;
                sr += x[base + j];
                sg += x[HWT + base + j];
                sb += x[2*HWT + base + j];
            }
        }
    }
#pragma unroll
    for (int o = 16; o > 0; o >>= 1) {
        cnt += __shfl_down_sync(0xffffffffu, cnt, o);
        sr  += __shfl_down_sync(0xffffffffu, sr,  o);
        sg  += __shfl_down_sync(0xffffffffu, sg,  o);
        sb  += __shfl_down_sync(0xffffffffu, sb,  o);
    }
    if ((threadIdx.x & 31) == 0) {
        atomicAdd(&g_cnt, cnt);
        atomicAdd(&g_sumr, sr);
        atomicAdd(&g_sumg, sg);
        atomicAdd(&g_sumb, sb);
    }
}

__global__ void k_avg() {
    float c = (float)g_cnt;
    float avg = (0.299f * g_sumr + 0.587f * g_sumg + 0.114f * g_sumb) / c;
    g_avg = avg;
    g_invavg = 1.0f / avg;
}

// ---------------- one row's 10 plane values (scalar per thread) ----------------
__device__ __forceinline__ void vrow(const float* __restrict__ x, int yy, int c,
                                     float inva, float v[10]) {
    float a0 = x[0*HWT + yy*WW + c];
    float a1 = x[1*HWT + yy*WW + c];
    float a2 = x[2*HWT + yy*WW + c];
    float d  = g_dc[yy*WW + c];
    float p = fmaf(-OMEGA * inva, d, 1.0f);
    v[0] = p;
    v[1] = a0; v[2] = a1; v[3] = a2;
    v[4] = p * a0; v[5] = p * a1; v[6] = p * a2;
    v[7] = a0 * a0; v[8] = a1 * a1; v[9] = a2 * a2;
}

// ---------------- vertical rolling box sums of the 10 planes ----------------
#define VS 16
__global__ void __launch_bounds__(256) k_vpass(const float* __restrict__ x) {
    int c  = blockIdx.x * 256 + threadIdx.x;
    int y0 = blockIdx.y * VS;
    float inva = g_invavg;
    float s[10];
#pragma unroll
    for (int p = 0; p < 10; p++) s[p] = 0.f;

    bool interior = (y0 >= RG + 1) && (y0 + VS - 1 + RG < HH);

    int ylo = y0 - RG; if (ylo < 0) ylo = 0;
    int yhi = y0 + RG; if (yhi > HH - 1) yhi = HH - 1;
#pragma unroll 4
    for (int yy = ylo; yy <= yhi; yy++) {
        float v[10];
        vrow(x, yy, c, inva, v);
#pragma unroll
        for (int p = 0; p < 10; p++) s[p] += v[p];
    }

    if (interior) {
#pragma unroll
        for (int p = 0; p < 10; p++)
            g_vsum[p*HWT + y0*WW + c] = s[p];
#pragma unroll 3
        for (int k = 1; k < VS; k++) {
            int y = y0 + k;
            float va[10], vs[10];
            vrow(x, y + RG, c, inva, va);
            vrow(x, y - RG - 1, c, inva, vs);
#pragma unroll
            for (int p = 0; p < 10; p++) s[p] += va[p] - vs[p];
#pragma unroll
            for (int p = 0; p < 10; p++)
                g_vsum[p*HWT + y*WW + c] = s[p];
        }
    } else {
        for (int k = 0; k < VS; k++) {
            int y = y0 + k;
            if (k > 0) {
                int ya = y + RG;
                if (ya < HH) {
                    float v[10];
                    vrow(x, ya, c, inva, v);
#pragma unroll
                    for (int p = 0; p < 10; p++) s[p] += v[p];
                }
                int yr = y - RG - 1;
                if (yr >= 0) {
                    float v[10];
                    vrow(x, yr, c, inva, v);
#pragma unroll
                    for (int p = 0; p < 10; p++) s[p] -= v[p];
                }
            }
#pragma unroll
            for (int p = 0; p < 10; p++)
                g_vsum[p*HWT + y*WW + c] = s[p];
        }
    }
}

// ---------------- horizontal box sums (block scans, 2 planes/round) + epilogue ----------------
// one block per half-row: 1024 output cols + 60-col halo each side, zero-padded
#define SEG 1144
__global__ void __launch_bounds__(256) k_hfinal(const float* __restrict__ x,
                                                float* __restrict__ out) {
    __shared__ float sps[10][SEG];
    __shared__ float2 wpart[8];
    int row = blockIdx.y;
    int c0  = blockIdx.x * 1024;
    int s0  = c0 - RG;
    int t = threadIdx.x, lane = t & 31, wid = t >> 5;

    for (int pl = 0; pl < 10; pl += 2) {
        const float* __restrict__ srcA = g_vsum + (pl+0)*HWT + row*WW;
        const float* __restrict__ srcB = g_vsum + (pl+1)*HWT + row*WW;
        float carryA = 0.f, carryB = 0.f;
        for (int ch = 0; ch < 5; ch++) {
            int L = ch * 256 + t;
            int gc = s0 + L;
            float vA = 0.f, vB = 0.f;
            bool in = (L < SEG && gc >= 0 && gc < WW);
            if (in) { vA = srcA[gc]; vB = srcB[gc]; }
            float scA = vA, scB = vB;
#pragma unroll
            for (int o = 1; o < 32; o <<= 1) {
                float nA = __shfl_up_sync(0xffffffffu, scA, o);
                float nB = __shfl_up_sync(0xffffffffu, scB, o);
                if (lane >= o) { scA += nA; scB += nB; }
            }
            if (lane == 31) wpart[wid] = make_float2(scA, scB);
            __syncthreads();
            float offA = carryA, offB = carryB, totA = 0.f, totB = 0.f;
#pragma unroll
            for (int w = 0; w < 8; w++) {
                float2 pw = wpart[w];
                totA += pw.x; totB += pw.y;
                if (w < wid) { offA += pw.x; offB += pw.y; }
            }
            if (L < SEG) {
                sps[pl+0][L] = scA + offA;
                sps[pl+1][L] = scB + offB;
            }
            carryA += totA; carryB += totB;
            __syncthreads();
        }
    }

    float avg = g_avg;
    int ny = min(row + RG, HH - 1) - max(row - RG, 0) + 1;
#pragma unroll
    for (int j = 0; j < 4; j++) {
        int L = t + j * 256;          // 0..1023
        int gc = c0 + L;
        int hi = L + 2*RG;            // local index of gc+RG
        int lo = L - 1;               // local index of gc-RG-1
        float w0 = sps[0][hi] - (lo >= 0 ? sps[0][lo] : 0.f);
        float w1 = sps[1][hi] - (lo >= 0 ? sps[1][lo] : 0.f);
        float w2 = sps[2][hi] - (lo >= 0 ? sps[2][lo] : 0.f);
        float w3 = sps[3][hi] - (lo >= 0 ? sps[3][lo] : 0.f);
        float w4 = sps[4][hi] - (lo >= 0 ? sps[4][lo] : 0.f);
        float w5 = sps[5][hi] - (lo >= 0 ? sps[5][lo] : 0.f);
        float w6 = sps[6][hi] - (lo >= 0 ? sps[6][lo] : 0.f);
        float w7 = sps[7][hi] - (lo >= 0 ? sps[7][lo] : 0.f);
        float w8 = sps[8][hi] - (lo >= 0 ? sps[8][lo] : 0.f);
        float w9 = sps[9][hi] - (lo >= 0 ? sps[9][lo] : 0.f);
        int nx = min(gc + RG, WW - 1) - max(gc - RG, 0) + 1;
        float invN = __fdividef(1.0f, (float)(nx * ny));
        float mp = w0 * invN;
        float mi, mpi, mii, cip, cii, a, b, xi, rt, yv;
        // ch 0
        mi = w1 * invN; mpi = w4 * invN; mii = w7 * invN;
        cip = mpi - mp * mi; cii = mii - mi * mi;
        a = __fdividef(cip, cii + EPSG); b = mp - a * mi;
        xi = x[0*HWT + row*WW + gc];
        rt = fminf(fmaxf(a * xi + b, 0.0f), 1.0f); rt = fmaxf(rt, 0.1f);
        yv = __fdividef(xi - avg, rt) + avg;
        out[0*HWT + row*WW + gc] = fminf(fmaxf(yv, 0.0f), 1.0f);
        // ch 1
        mi = w2 * invN; mpi = w5 * invN; mii = w8 * invN;
        cip = mpi - mp * mi; cii = mii - mi * mi;
        a = __fdividef(cip, cii + EPSG); b = mp - a * mi;
        xi = x[1*HWT + row*WW + gc];
        rt = fminf(fmaxf(a * xi + b, 0.0f), 1.0f); rt = fmaxf(rt, 0.1f);
        yv = __fdividef(xi - avg, rt) + avg;
        out[1*HWT + row*WW + gc] = fminf(fmaxf(yv, 0.0f), 1.0f);
        // ch 2
        mi = w3 * invN; mpi = w6 * invN; mii = w9 * invN;
        cip = mpi - mp * mi; cii = mii - mi * mi;
        a = __fdividef(cip, cii + EPSG); b = mp - a * mi;
        xi = x[2*HWT + row*WW + gc];
        rt = fminf(fmaxf(a * xi + b, 0.0f), 1.0f); rt = fmaxf(rt, 0.1f);
        yv = __fdividef(xi - avg, rt) + avg;
        out[2*HWT + row*WW + gc] = fminf(fmaxf(yv, 0.0f), 1.0f);
    }
}

// ---------------- launch ----------------
extern "C" void kernel_launch(void* const* d_in, const int* in_sizes, int n_in,
                              void* d_out, int out_size) {
    const float* x = (const float*)d_in[0];
    float* out = (float*)d_out;

    k_init<<<2048, 256>>>();
    k_cmin_hmin<<<dim3(8, 2048), 256>>>(x);
    k_vmin_hist<<<dim3(8, 128), 256>>>();
    k_scan1<<<1, 256>>>();
    k_hist2<<<1024, 256>>>();
    k_chunks<<<1024, 128>>>();
    k_scan2<<<1, 1024>>>();
    k_mask<<<1024, 256>>>(x);
    k_avg<<<1, 1>>>();
    k_vpass<<<dim3(8, 128), 256>>>(x);
    k_hfinal<<<dim3(2, 2048), 256>>>(x, out);
}